// round 9
// baseline (speedup 1.0000x reference)
#include <cuda_runtime.h>
#include <cstdint>

#define NATOMS_V 100
#define DIM    200
#define NPAD   256       // global col stride
#define CPAD   208       // computed cols (200 real + 8 pad)
#define LHID   6
#define LPRED  3
#define NADD   4
#define DPRED  204
#define NA     32
#define NTOT   8192
#define CK     16
#define NCH    13        // 12 x 16k + 1 x 8k
#define TPB    1024
#define ROWS   64        // rows per CTA (2 molecules)

typedef unsigned long long ull;

// ---------- device scratch ----------
__device__ float g_act[2][NTOT][NPAD];
__device__ float g_wpad[9][DIM][NPAD];
__device__ float g_bpad[9][NPAD];

// ---------- helpers ----------
__device__ __forceinline__ void ffma2(ull& d, ull a, ull b) {
    asm("fma.rn.f32x2 %0, %1, %2, %0;" : "+l"(d) : "l"(a), "l"(b));
}
__device__ __forceinline__ ull dupf(float v) {
    float2 t = make_float2(v, v);
    return *(ull*)&t;
}
__device__ __forceinline__ uint32_t smaddr(const void* p) {
    return (uint32_t)__cvta_generic_to_shared(p);
}
__device__ __forceinline__ void cp_async16(uint32_t s, const void* g) {
    asm volatile("cp.async.cg.shared.global [%0], [%1], 16;" :: "r"(s), "l"(g));
}
__device__ __forceinline__ void cp_commit() { asm volatile("cp.async.commit_group;" ::: "memory"); }
__device__ __forceinline__ void cp_wait0()  { asm volatile("cp.async.wait_group 0;" ::: "memory"); }

struct LayerSmem {
    float  sA[2][ROWS][CK];     //  8.2 KB  A chunk ring
    float  sW[2][CK][CPAD];     // 26.6 KB  W chunk ring
    float  sHV[ROWS][CPAD];     // 53.2 KB  GEMM result for epilogue
    float2 sMd[2][NA][NA];      // 16.4 KB  message matrices (dup)
    float  sGam[ROWS];
    float  spv[2][2][DPRED + 4];
    float  sred[2][16];
};   // ~108 KB -> 1 CTA/SM (32 warps)

// ---------- prep ----------
__global__ void prep_kernel(const float* __restrict__ Waw, const float* __restrict__ Wab,
                            const float* __restrict__ Wow, const float* __restrict__ Wob)
{
    const int stride = gridDim.x * blockDim.x;
    for (int idx = blockIdx.x * blockDim.x + threadIdx.x; idx < 9 * DIM * NPAD; idx += stride) {
        const int l = idx / (DIM * NPAD);
        const int rem = idx - l * DIM * NPAD;
        const int k = rem >> 8, c = rem & 255;
        float v = 0.f;
        if (c < DIM)
            v = (l < LHID) ? Waw[(l * DIM + k) * DIM + c]
                           : Wow[((l - LHID) * DIM + k) * DIM + c];
        g_wpad[l][k][c] = v;
    }
    for (int idx = blockIdx.x * blockDim.x + threadIdx.x; idx < 9 * NPAD; idx += stride) {
        const int l = idx >> 8, c = idx & 255;
        float v = 0.f;
        if (c < DIM)
            v = (l < LHID) ? Wab[l * DIM + c] : Wob[(l - LHID) * DIM + c];
        g_bpad[l][c] = v;
    }
}

// ---------- embed ----------
__global__ void embed_kernel(const int* __restrict__ atoms,
                             const float* __restrict__ embed_atom)
{
    int idx = blockIdx.x * blockDim.x + threadIdx.x;
    if (idx >= NTOT * DIM) return;
    const int row = idx / DIM, c = idx - row * DIM;
    g_act[0][row][c] = embed_atom[atoms[row] * DIM + c];
}

// ---------- layer kernel: 64x208 GEMM tile + fused epilogue, 1024 thr ----------
// 32 warps = 8 row-groups (8 rows) x 4 col-groups (52 cols / 26 lanes).
// MODE 0: hidden (relu -> mix -> normalize -> g_act[pout])
// MODE 1: out layer (relu -> g_act[pout])
// MODE 2: final (relu -> molecule sum -> pred MLP -> out)
template<int MODE>
__global__ __launch_bounds__(TPB, 1)
void layer_kernel(int l, int pin, int pout,
                  const int*   __restrict__ atoms,
                  const float* __restrict__ dist,
                  const float* __restrict__ gamma_tab,
                  const float* __restrict__ adducts,
                  const float* __restrict__ W_pred_w,
                  const float* __restrict__ W_pred_b,
                  const float* __restrict__ W_prop_w,
                  const float* __restrict__ W_prop_b,
                  float* __restrict__ out)
{
    extern __shared__ char smraw[];
    LayerSmem& sm = *reinterpret_cast<LayerSmem*>(smraw);

    const int tid  = threadIdx.x;
    const int warp = tid >> 5, lane = tid & 31;
    const int row0 = blockIdx.x * ROWS;
    const int rg = warp >> 2, cg = warp & 3;
    const int r0 = rg * 8;
    const bool act = (lane < 26);
    const int wc = cg * 52 + 2 * (act ? lane : 0);    // computed col pair

    // stage chunk c into ring slot buf
    auto stage = [&](int c, int buf) {
        const int k0 = c * CK;
        const int cs = (c == NCH - 1) ? 8 : CK;
        const int perRow = cs / 4;                 // 4 or 2 cp16 per row
        const int nA = ROWS * perRow;              // 256 or 128
        if (tid < nA) {
            const int row = tid / perRow, q = (tid % perRow) * 4;
            cp_async16(smaddr(&sm.sA[buf][row][q]), &g_act[pin][row0 + row][k0 + q]);
        }
        const int nW = cs * 52;                    // 832 or 416 cp16
        for (int o = tid; o < nW; o += TPB) {
            const int kr = o / 52, c4 = (o - kr * 52) * 4;
            cp_async16(smaddr(&sm.sW[buf][kr][c4]), &g_wpad[l][k0 + kr][c4]);
        }
    };

    stage(0, 0);
    cp_commit();

    if (MODE == 0) {   // message-matrix prep overlaps stage 0
        if (tid < ROWS) sm.sGam[tid] = gamma_tab[l * NATOMS_V + atoms[row0 + tid]];
        __syncthreads();
        #pragma unroll
        for (int i = 0; i < 2; i++) {
            const int idx = tid + i * TPB;
            const int mol = idx >> 10, ii = (idx >> 5) & 31, jj = idx & 31;
            const float d = dist[(row0 + mol * 32 + ii) * NTOT + row0 + mol * 32 + jj];
            const float e = __expf(-sm.sGam[mol * 32 + jj] * d * d);
            sm.sMd[mol][ii][jj] = make_float2(e, e);
        }
    }

    ull acc[8];
    #pragma unroll
    for (int r = 0; r < 8; r++) acc[r] = 0ull;

    for (int c = 0; c < NCH; c++) {
        cp_wait0();
        __syncthreads();
        if (c + 1 < NCH) stage(c + 1, (c + 1) & 1);
        cp_commit();
        const int buf = c & 1;
        const int cs = (c == NCH - 1) ? 8 : CK;
        for (int kk = 0; kk < cs; kk += 4) {
            float4 a4[8];
            #pragma unroll
            for (int r = 0; r < 8; r++)
                a4[r] = *(const float4*)&sm.sA[buf][r0 + r][kk];   // broadcast LDS.128
            #pragma unroll
            for (int q = 0; q < 4; q++) {
                const ull w0 = *(const ull*)&sm.sW[buf][kk + q][wc];
                #pragma unroll
                for (int r = 0; r < 8; r++)
                    ffma2(acc[r], dupf(((const float*)&a4[r])[q]), w0);
            }
        }
    }

    const float2 bb = *(const float2*)&g_bpad[l][wc];

    if (MODE == 1) {
        if (act) {
            #pragma unroll
            for (int r = 0; r < 8; r++) {
                float2 v = *(float2*)&acc[r];
                *(float2*)&g_act[pout][row0 + r0 + r][wc] =
                    make_float2(fmaxf(v.x + bb.x, 0.f), fmaxf(v.y + bb.y, 0.f));
            }
        }
        return;
    }

    // MODE 0 / 2: hv to smem
    if (act) {
        #pragma unroll
        for (int r = 0; r < 8; r++) {
            float2 v = *(float2*)&acc[r];
            *(float2*)&sm.sHV[r0 + r][wc] =
                make_float2(fmaxf(v.x + bb.x, 0.f), fmaxf(v.y + bb.y, 0.f));
        }
    }
    __syncthreads();

    if (MODE == 0) {
        // mix + normalize: warp -> (mol = warp>>4, 2 rows), full 200 cols
        const int mol = warp >> 4;
        const int i0 = (warp & 15) * 2;
        const bool has3 = (lane < 4);
        const int m0 = 2 * lane, m1 = m0 + 64, m2 = m0 + 128, m3 = 192 + 2 * lane;
        const float (*hv)[CPAD] = (const float (*)[CPAD])&sm.sHV[mol * 32];

        ull a2[2][4];
        #pragma unroll
        for (int r = 0; r < 2; r++) {
            a2[r][0] = *(const ull*)&hv[i0 + r][m0];
            a2[r][1] = *(const ull*)&hv[i0 + r][m1];
            a2[r][2] = *(const ull*)&hv[i0 + r][m2];
            a2[r][3] = has3 ? *(const ull*)&hv[i0 + r][m3] : 0ull;
        }
        #pragma unroll 4
        for (int j = 0; j < NA; j++) {
            ull mm0 = *(const ull*)&sm.sMd[mol][i0][j];
            ull mm1 = *(const ull*)&sm.sMd[mol][i0 + 1][j];
            ull h0 = *(const ull*)&hv[j][m0];
            ull h1 = *(const ull*)&hv[j][m1];
            ull h2 = *(const ull*)&hv[j][m2];
            ffma2(a2[0][0], mm0, h0); ffma2(a2[1][0], mm1, h0);
            ffma2(a2[0][1], mm0, h1); ffma2(a2[1][1], mm1, h1);
            ffma2(a2[0][2], mm0, h2); ffma2(a2[1][2], mm1, h2);
            if (has3) {
                ull h3 = *(const ull*)&hv[j][m3];
                ffma2(a2[0][3], mm0, h3); ffma2(a2[1][3], mm1, h3);
            }
        }
        #pragma unroll
        for (int r = 0; r < 2; r++) {
            float ss = 0.f;
            #pragma unroll
            for (int u = 0; u < 4; u++) {
                float2 v = *(float2*)&a2[r][u];
                ss += v.x * v.x + v.y * v.y;
            }
            #pragma unroll
            for (int o = 16; o > 0; o >>= 1)
                ss += __shfl_xor_sync(0xffffffffu, ss, o);
            const float scale = 1.f / fmaxf(sqrtf(ss), 1e-12f);
            const int grow = row0 + mol * 32 + i0 + r;
            #pragma unroll
            for (int u = 0; u < 3; u++) {
                float2 v = *(float2*)&a2[r][u];
                *(float2*)&g_act[pout][grow][m0 + 64 * u] =
                    make_float2(v.x * scale, v.y * scale);
            }
            if (has3) {
                float2 v = *(float2*)&a2[r][3];
                *(float2*)&g_act[pout][grow][m3] =
                    make_float2(v.x * scale, v.y * scale);
            }
        }
        return;
    }

    // MODE 2: 2 molecules per CTA, 512 threads each
    {
        const int mol = tid >> 9;
        const int col = tid & 511;
        if (col < DPRED) {
            float s;
            if (col < DIM) {
                s = 0.f;
                #pragma unroll 8
                for (int i = 0; i < NA; i++) s += sm.sHV[mol * 32 + i][col];
            } else {
                s = adducts[(2 * blockIdx.x + mol) * NADD + (col - DIM)];
            }
            sm.spv[0][mol][col] = s;
        }
        __syncthreads();

        int cur = 0;
        for (int lp = 0; lp < LPRED; lp++) {
            if (col < DPRED) {
                const float* Wp = W_pred_w + lp * DPRED * DPRED;
                float a = W_pred_b[lp * DPRED + col];
                #pragma unroll 4
                for (int k = 0; k < DPRED; k++)
                    a += sm.spv[cur][mol][k] * Wp[k * DPRED + col];
                sm.spv[cur ^ 1][mol][col] = fmaxf(a, 0.f);
            }
            __syncthreads();
            cur ^= 1;
        }

        float p = (col < DPRED) ? sm.spv[cur][mol][col] * W_prop_w[col] : 0.f;
        #pragma unroll
        for (int o = 16; o > 0; o >>= 1)
            p += __shfl_xor_sync(0xffffffffu, p, o);
        if (lane == 0) sm.sred[mol][warp & 15] = p;
        __syncthreads();
        if ((tid & 511) == 0) {
            float s = 0.f;
            #pragma unroll
            for (int w = 0; w < 16; w++) s += sm.sred[mol][w];
            out[2 * blockIdx.x + mol] = s + W_prop_b[0];
        }
    }
}

// ---------- launch ----------
extern "C" void kernel_launch(void* const* d_in, const int* in_sizes, int n_in,
                              void* d_out, int out_size)
{
    const int*   atoms      = (const int*)  d_in[0];
    const float* dist       = (const float*)d_in[1];
    const float* adducts    = (const float*)d_in[2];
    const float* embed_atom = (const float*)d_in[3];
    const float* gamma_tab  = (const float*)d_in[4];
    const float* W_atom_w   = (const float*)d_in[5];
    const float* W_atom_b   = (const float*)d_in[6];
    const float* W_out_w    = (const float*)d_in[7];
    const float* W_out_b    = (const float*)d_in[8];
    const float* W_pred_w   = (const float*)d_in[9];
    const float* W_pred_b   = (const float*)d_in[10];
    const float* W_prop_w   = (const float*)d_in[11];
    const float* W_prop_b   = (const float*)d_in[12];
    float* out = (float*)d_out;

    const int smem = (int)sizeof(LayerSmem);
    cudaFuncSetAttribute(layer_kernel<0>, cudaFuncAttributeMaxDynamicSharedMemorySize, smem);
    cudaFuncSetAttribute(layer_kernel<1>, cudaFuncAttributeMaxDynamicSharedMemorySize, smem);
    cudaFuncSetAttribute(layer_kernel<2>, cudaFuncAttributeMaxDynamicSharedMemorySize, smem);

    prep_kernel<<<512, 256>>>(W_atom_w, W_atom_b, W_out_w, W_out_b);
    embed_kernel<<<(NTOT * DIM + 511) / 512, 512>>>(atoms, embed_atom);

    const int grid = NTOT / ROWS;   // 128
    for (int l = 0; l < LHID; l++)
        layer_kernel<0><<<grid, TPB, smem>>>(l, l & 1, (l & 1) ^ 1,
            atoms, dist, gamma_tab, adducts, W_pred_w, W_pred_b, W_prop_w, W_prop_b, out);

    layer_kernel<1><<<grid, TPB, smem>>>(6, 0, 1,
        atoms, dist, gamma_tab, adducts, W_pred_w, W_pred_b, W_prop_w, W_prop_b, out);
    layer_kernel<1><<<grid, TPB, smem>>>(7, 1, 0,
        atoms, dist, gamma_tab, adducts, W_pred_w, W_pred_b, W_prop_w, W_prop_b, out);
    layer_kernel<2><<<grid, TPB, smem>>>(8, 0, 0,
        atoms, dist, gamma_tab, adducts, W_pred_w, W_pred_b, W_prop_w, W_prop_b, out);
}

// round 17
// speedup vs baseline: 1.6036x; 1.6036x over previous
#include <cuda_runtime.h>
#include <cuda_bf16.h>
#include <cstdint>

#define NATOMS_V 100
#define DIM    200
#define NPAD   256        // g_act col stride
#define NC     208        // computed cols (26 n-tiles)
#define KCH    32
#define NCHUNK 7          // K padded to 224
#define LHID   6
#define LPRED  3
#define NADD   4
#define DPRED  204
#define NA     32
#define NTOT   8192
#define MROWS  64
#define TPB    256
#define HVSTR  212        // hv smem stride (floats)

typedef unsigned int u32;
typedef unsigned long long ull;

// ---------------- device scratch ----------------
__device__ float         g_act[2][NTOT][NPAD];          // fp32 activations (pads stay 0)
__device__ __nv_bfloat16 g_wb[9][2][NCHUNK][NC][KCH];   // W split hi/lo, [n][k] per chunk
__device__ float         g_bpad[9][NPAD];

// ---------------- helpers ----------------
__device__ __forceinline__ void ffma2(ull& d, ull a, ull b) {
    asm("fma.rn.f32x2 %0, %1, %2, %0;" : "+l"(d) : "l"(a), "l"(b));
}
__device__ __forceinline__ ull dupf(float v) {
    float2 t = make_float2(v, v); return *(ull*)&t;
}
__device__ __forceinline__ u32 smem_u32(const void* p) {
    return (u32)__cvta_generic_to_shared(p);
}
__device__ __forceinline__ void cp_async16(u32 s, const void* g) {
    asm volatile("cp.async.cg.shared.global [%0], [%1], 16;" :: "r"(s), "l"(g));
}
__device__ __forceinline__ void cp_commit() { asm volatile("cp.async.commit_group;" ::: "memory"); }
__device__ __forceinline__ void cp_wait0()  { asm volatile("cp.async.wait_group 0;" ::: "memory"); }

__device__ __forceinline__ void ldmx4(u32* r, u32 addr) {
    asm volatile("ldmatrix.sync.aligned.m8n8.x4.shared.b16 {%0,%1,%2,%3}, [%4];"
        : "=r"(r[0]), "=r"(r[1]), "=r"(r[2]), "=r"(r[3]) : "r"(addr));
}
__device__ __forceinline__ void mma_bf16(float* c, const u32* a, u32 b0, u32 b1) {
    asm volatile("mma.sync.aligned.m16n8k16.row.col.f32.bf16.bf16.f32 "
        "{%0,%1,%2,%3}, {%4,%5,%6,%7}, {%8,%9}, {%0,%1,%2,%3};"
        : "+f"(c[0]), "+f"(c[1]), "+f"(c[2]), "+f"(c[3])
        : "r"(a[0]), "r"(a[1]), "r"(a[2]), "r"(a[3]), "r"(b0), "r"(b1));
}
__device__ __forceinline__ unsigned short bfbits(float x) {
    __nv_bfloat16 b = __float2bfloat16(x);
    return *reinterpret_cast<unsigned short*>(&b);
}
__device__ __forceinline__ float bfval(unsigned short u) {
    __nv_bfloat16 b; *reinterpret_cast<unsigned short*>(&b) = u;
    return __bfloat162float(b);
}

// ---------------- smem layout (bytes) ----------------
// GEMM: W ring [buf][s][n:208][k:32] rows padded to 80B; A ring [buf][s][row:64][k:32]
// EPI : hv fp32 [64][HVSTR] unioned at offset 0
#define OFF_W   0
#define W_BYTES (2 * 2 * NC * 80)          // 66560
#define OFF_A   W_BYTES
#define A_BYTES (2 * 2 * MROWS * 80)       // 20480
#define OFF_MD  (OFF_W + W_BYTES + A_BYTES)   // 87040
#define OFF_GAM (OFF_MD + 2 * NA * NA * 4)    // 95232
#define SMEM_SZ (OFF_GAM + 256)               // 95488

// ---------------- prep: split + transpose + pad W, pad bias ----------------
__global__ void prep_kernel(const float* __restrict__ Waw, const float* __restrict__ Wab,
                            const float* __restrict__ Wow, const float* __restrict__ Wob)
{
    const int total = 9 * NCHUNK * NC * KCH;
    for (int idx = blockIdx.x * blockDim.x + threadIdx.x; idx < total;
         idx += gridDim.x * blockDim.x) {
        const int k  = idx & 31;
        int t = idx >> 5;
        const int n  = t % NC;  t /= NC;
        const int ch = t % NCHUNK;
        const int l  = t / NCHUNK;
        const int kg = ch * KCH + k;
        float v = 0.f;
        if (n < DIM && kg < DIM)
            v = (l < LHID) ? Waw[(l * DIM + kg) * DIM + n]
                           : Wow[((l - LHID) * DIM + kg) * DIM + n];
        const unsigned short hb = bfbits(v);
        const unsigned short lb = bfbits(v - bfval(hb));
        *(unsigned short*)&g_wb[l][0][ch][n][k] = hb;
        *(unsigned short*)&g_wb[l][1][ch][n][k] = lb;
    }
    for (int idx = blockIdx.x * blockDim.x + threadIdx.x; idx < 9 * NPAD;
         idx += gridDim.x * blockDim.x) {
        const int l = idx >> 8, c = idx & 255;
        float v = 0.f;
        if (c < DIM) v = (l < LHID) ? Wab[l * DIM + c] : Wob[(l - LHID) * DIM + c];
        g_bpad[l][c] = v;
    }
}

// ---------------- embed ----------------
__global__ void embed_kernel(const int* __restrict__ atoms,
                             const float* __restrict__ embed_atom)
{
    int idx = blockIdx.x * blockDim.x + threadIdx.x;
    if (idx >= NTOT * DIM) return;
    const int row = idx / DIM, c = idx - row * DIM;
    g_act[0][row][c] = embed_atom[atoms[row] * DIM + c];
}

// ---------------- layer kernel: HMMA GEMM (64x208) + fused epilogue ----------------
// warps: mg = warp>>2 (2 groups of 32 rows = 2 m-tiles each), ng = warp&3
// n-tile ranges: {0-6, 7-13, 14-19, 20-25}
// MODE 0: relu -> mix -> normalize -> g_act[pout];  MODE 1: relu -> g_act[pout]
template<int MODE>
__global__ __launch_bounds__(TPB, 1)
void layer_kernel(int l, int pin, int pout,
                  const int*   __restrict__ atoms,
                  const float* __restrict__ dist,
                  const float* __restrict__ gamma_tab)
{
    extern __shared__ __align__(1024) char smraw[];
    const u32 sb = smem_u32(smraw);
    const int tid  = threadIdx.x;
    const int warp = tid >> 5, lane = tid & 31;
    const int row0 = blockIdx.x * MROWS;
    const int mg = warp >> 2, ng = warp & 3;
    const int nstart = (ng < 2) ? ng * 7 : 14 + (ng - 2) * 6;
    const int ncnt   = (ng < 2) ? 7 : 6;

    float* smMD  = (float*)(smraw + OFF_MD);
    float* smGAM = (float*)(smraw + OFF_GAM);
    float* hv    = (float*)smraw;                 // union with GEMM buffers

    auto stageW = [&](int ch, int buf) {
        // 2 splits x 208 rows x 4 cp16 = 1664
        for (int o = tid; o < 1664; o += TPB) {
            const int s  = (o >= 832) ? 1 : 0;
            const int o2 = o - s * 832;
            const int n  = o2 >> 2, q = (o2 & 3) * 16;
            cp_async16(sb + OFF_W + (u32)(((buf * 2 + s) * NC + n) * 80 + q),
                       (const char*)&g_wb[l][s][ch][n][0] + q);
        }
    };
    auto stageA = [&](int ch, int buf) {
        const int row = tid >> 2, seg = tid & 3;
        const float* src = &g_act[pin][row0 + row][ch * KCH + seg * 8];
        float4 f0 = *(const float4*)src;
        float4 f1 = *(const float4*)(src + 4);
        float v[8] = {f0.x, f0.y, f0.z, f0.w, f1.x, f1.y, f1.z, f1.w};
        unsigned short h[8], lo[8];
        #pragma unroll
        for (int i = 0; i < 8; i++) {
            h[i]  = bfbits(v[i]);
            lo[i] = bfbits(v[i] - bfval(h[i]));
        }
        uint4 H = make_uint4(h[0] | (h[1] << 16), h[2] | (h[3] << 16),
                             h[4] | (h[5] << 16), h[6] | (h[7] << 16));
        uint4 L = make_uint4(lo[0] | (lo[1] << 16), lo[2] | (lo[3] << 16),
                             lo[4] | (lo[5] << 16), lo[6] | (lo[7] << 16));
        *(uint4*)(smraw + OFF_A + ((buf * 2 + 0) * MROWS + row) * 80 + seg * 16) = H;
        *(uint4*)(smraw + OFF_A + ((buf * 2 + 1) * MROWS + row) * 80 + seg * 16) = L;
    };

    stageW(0, 0);
    stageA(0, 0);
    cp_commit();

    if (MODE == 0) {   // gamma + message matrices (overlaps stage 0)
        if (tid < MROWS) smGAM[tid] = gamma_tab[l * NATOMS_V + atoms[row0 + tid]];
        __syncthreads();
        #pragma unroll
        for (int i = 0; i < 8; i++) {
            const int idx = tid + i * TPB;
            const int mol = idx >> 10, ii = (idx >> 5) & 31, jj = idx & 31;
            const float d = dist[(row0 + mol * 32 + ii) * NTOT + row0 + mol * 32 + jj];
            smMD[idx] = __expf(-smGAM[mol * 32 + jj] * d * d);
        }
    }

    float c[2][7][4];
    #pragma unroll
    for (int mt = 0; mt < 2; mt++)
        #pragma unroll
        for (int i = 0; i < 7; i++)
            #pragma unroll
            for (int e = 0; e < 4; e++) c[mt][i][e] = 0.f;

    for (int ch = 0; ch < NCHUNK; ch++) {
        cp_wait0();
        __syncthreads();
        if (ch + 1 < NCHUNK) { stageW(ch + 1, (ch + 1) & 1); stageA(ch + 1, (ch + 1) & 1); }
        cp_commit();
        const int buf = ch & 1;

        // A fragments: [mt][kt][split][4]
        u32 af[2][2][2][4];
        #pragma unroll
        for (int mt = 0; mt < 2; mt++)
            #pragma unroll
            for (int kt = 0; kt < 2; kt++)
                #pragma unroll
                for (int s = 0; s < 2; s++) {
                    const u32 a = sb + OFF_A
                        + (u32)(((buf * 2 + s) * MROWS + mg * 32 + mt * 16 + (lane & 15)) * 80
                                + (kt * 16 + ((lane >> 4) * 8)) * 2);
                    ldmx4(af[mt][kt][s], a);
                }

        #pragma unroll
        for (int i = 0; i < 7; i++) {
            if (i < ncnt) {
                const int nt = nstart + i;
                u32 bfr[2][4];
                #pragma unroll
                for (int s = 0; s < 2; s++) {
                    const u32 a = sb + OFF_W
                        + (u32)(((buf * 2 + s) * NC + nt * 8 + (lane & 7)) * 80
                                + ((lane >> 3) * 8) * 2);
                    ldmx4(bfr[s], a);
                }
                #pragma unroll
                for (int kt = 0; kt < 2; kt++) {
                    const u32 b0h = bfr[0][kt * 2], b1h = bfr[0][kt * 2 + 1];
                    const u32 b0l = bfr[1][kt * 2], b1l = bfr[1][kt * 2 + 1];
                    #pragma unroll
                    for (int mt = 0; mt < 2; mt++) mma_bf16(c[mt][i], af[mt][kt][0], b0h, b1h);
                    #pragma unroll
                    for (int mt = 0; mt < 2; mt++) mma_bf16(c[mt][i], af[mt][kt][0], b0l, b1l);
                    #pragma unroll
                    for (int mt = 0; mt < 2; mt++) mma_bf16(c[mt][i], af[mt][kt][1], b0h, b1h);
                }
            }
        }
    }
    __syncthreads();   // all warps done reading GEMM smem (hv union safe)

    const int qrow = lane >> 2, qc = 2 * (lane & 3);

    if (MODE == 1) {
        #pragma unroll
        for (int mt = 0; mt < 2; mt++)
            #pragma unroll
            for (int i = 0; i < 7; i++) {
                if (i < ncnt) {
                    const int nt = nstart + i;
                    if (nt < 25) {
                        const int col = nt * 8 + qc;
                        const float2 bv = *(const float2*)&g_bpad[l][col];
                        const int r = row0 + mg * 32 + mt * 16 + qrow;
                        *(float2*)&g_act[pout][r][col] =
                            make_float2(fmaxf(c[mt][i][0] + bv.x, 0.f),
                                        fmaxf(c[mt][i][1] + bv.y, 0.f));
                        *(float2*)&g_act[pout][r + 8][col] =
                            make_float2(fmaxf(c[mt][i][2] + bv.x, 0.f),
                                        fmaxf(c[mt][i][3] + bv.y, 0.f));
                    }
                }
            }
        return;
    }

    // MODE 0: hv to smem
    #pragma unroll
    for (int mt = 0; mt < 2; mt++)
        #pragma unroll
        for (int i = 0; i < 7; i++) {
            if (i < ncnt) {
                const int nt = nstart + i;
                if (nt < 25) {
                    const int col = nt * 8 + qc;
                    const float2 bv = *(const float2*)&g_bpad[l][col];
                    const int r = mg * 32 + mt * 16 + qrow;
                    *(float2*)&hv[r * HVSTR + col] =
                        make_float2(fmaxf(c[mt][i][0] + bv.x, 0.f),
                                    fmaxf(c[mt][i][1] + bv.y, 0.f));
                    *(float2*)&hv[(r + 8) * HVSTR + col] =
                        make_float2(fmaxf(c[mt][i][2] + bv.x, 0.f),
                                    fmaxf(c[mt][i][3] + bv.y, 0.f));
                }
            }
        }
    __syncthreads();

    // mix + normalize: warp -> mol = warp>>2, 8 rows (2 passes of 4)
    const int mol = warp >> 2;
    const int ib  = (warp & 3) * 8;
    const bool has3 = (lane < 4);
    const int m0 = 2 * lane, m1 = m0 + 64, m2 = m0 + 128, m3 = 192 + 2 * lane;
    const float* hvm = hv + (mol * 32) * HVSTR;
    const float* md  = smMD + mol * 1024;

    #pragma unroll
    for (int pass = 0; pass < 2; pass++) {
        const int i0 = ib + pass * 4;
        ull a2[4][4];
        #pragma unroll
        for (int r = 0; r < 4; r++) {
            a2[r][0] = *(const ull*)&hvm[(i0 + r) * HVSTR + m0];
            a2[r][1] = *(const ull*)&hvm[(i0 + r) * HVSTR + m1];
            a2[r][2] = *(const ull*)&hvm[(i0 + r) * HVSTR + m2];
            a2[r][3] = has3 ? *(const ull*)&hvm[(i0 + r) * HVSTR + m3] : 0ull;
        }
        #pragma unroll 4
        for (int j = 0; j < NA; j++) {
            ull mm[4];
            #pragma unroll
            for (int r = 0; r < 4; r++) mm[r] = dupf(md[(i0 + r) * 32 + j]);
            const ull h0 = *(const ull*)&hvm[j * HVSTR + m0];
            const ull h1 = *(const ull*)&hvm[j * HVSTR + m1];
            const ull h2 = *(const ull*)&hvm[j * HVSTR + m2];
            #pragma unroll
            for (int r = 0; r < 4; r++) {
                ffma2(a2[r][0], mm[r], h0);
                ffma2(a2[r][1], mm[r], h1);
                ffma2(a2[r][2], mm[r], h2);
            }
            if (has3) {
                const ull h3 = *(const ull*)&hvm[j * HVSTR + m3];
                #pragma unroll
                for (int r = 0; r < 4; r++) ffma2(a2[r][3], mm[r], h3);
            }
        }
        #pragma unroll
        for (int r = 0; r < 4; r++) {
            float ss = 0.f;
            #pragma unroll
            for (int u = 0; u < 4; u++) {
                float2 v = *(float2*)&a2[r][u];
                ss += v.x * v.x + v.y * v.y;
            }
            #pragma unroll
            for (int o = 16; o > 0; o >>= 1)
                ss += __shfl_xor_sync(0xffffffffu, ss, o);
            const float sc = 1.f / fmaxf(sqrtf(ss), 1e-12f);
            const int grow = row0 + mol * 32 + i0 + r;
            #pragma unroll
            for (int u = 0; u < 3; u++) {
                float2 v = *(float2*)&a2[r][u];
                *(float2*)&g_act[pout][grow][m0 + 64 * u] = make_float2(v.x * sc, v.y * sc);
            }
            if (has3) {
                float2 v = *(float2*)&a2[r][3];
                *(float2*)&g_act[pout][grow][m3] = make_float2(v.x * sc, v.y * sc);
            }
        }
    }
}

// ---------------- tail: molecule sum + pred MLP + out ----------------
__global__ __launch_bounds__(256) void tail_kernel(const float* __restrict__ adducts,
                                                   const float* __restrict__ W_pred_w,
                                                   const float* __restrict__ W_pred_b,
                                                   const float* __restrict__ W_prop_w,
                                                   const float* __restrict__ W_prop_b,
                                                   float* __restrict__ out)
{
    __shared__ float pv[2][DPRED + 4];
    __shared__ float red[8];
    const int m = blockIdx.x;
    const int tid = threadIdx.x;

    if (tid < DIM) {
        float s = 0.f;
        #pragma unroll 8
        for (int i = 0; i < NA; i++) s += g_act[1][m * NA + i][tid];
        pv[0][tid] = s;
    } else if (tid < DPRED) {
        pv[0][tid] = adducts[m * NADD + (tid - DIM)];
    }
    __syncthreads();

    int cur = 0;
    for (int lp = 0; lp < LPRED; lp++) {
        if (tid < DPRED) {
            const float* Wp = W_pred_w + lp * DPRED * DPRED;
            float a = W_pred_b[lp * DPRED + tid];
            #pragma unroll 4
            for (int k = 0; k < DPRED; k++)
                a += pv[cur][k] * Wp[k * DPRED + tid];
            pv[cur ^ 1][tid] = fmaxf(a, 0.f);
        }
        __syncthreads();
        cur ^= 1;
    }

    float p = (tid < DPRED) ? pv[cur][tid] * W_prop_w[tid] : 0.f;
    #pragma unroll
    for (int o = 16; o > 0; o >>= 1)
        p += __shfl_xor_sync(0xffffffffu, p, o);
    if ((tid & 31) == 0) red[tid >> 5] = p;
    __syncthreads();
    if (tid == 0) {
        float s = 0.f;
        #pragma unroll
        for (int w = 0; w < 8; w++) s += red[w];
        out[m] = s + W_prop_b[0];
    }
}

// ---------------- launch ----------------
extern "C" void kernel_launch(void* const* d_in, const int* in_sizes, int n_in,
                              void* d_out, int out_size)
{
    const int*   atoms      = (const int*)  d_in[0];
    const float* dist       = (const float*)d_in[1];
    const float* adducts    = (const float*)d_in[2];
    const float* embed_atom = (const float*)d_in[3];
    const float* gamma_tab  = (const float*)d_in[4];
    const float* W_atom_w   = (const float*)d_in[5];
    const float* W_atom_b   = (const float*)d_in[6];
    const float* W_out_w    = (const float*)d_in[7];
    const float* W_out_b    = (const float*)d_in[8];
    const float* W_pred_w   = (const float*)d_in[9];
    const float* W_pred_b   = (const float*)d_in[10];
    const float* W_prop_w   = (const float*)d_in[11];
    const float* W_prop_b   = (const float*)d_in[12];
    float* out = (float*)d_out;

    cudaFuncSetAttribute(layer_kernel<0>, cudaFuncAttributeMaxDynamicSharedMemorySize, SMEM_SZ);
    cudaFuncSetAttribute(layer_kernel<1>, cudaFuncAttributeMaxDynamicSharedMemorySize, SMEM_SZ);

    prep_kernel<<<512, 512>>>(W_atom_w, W_atom_b, W_out_w, W_out_b);
    embed_kernel<<<(NTOT * DIM + 511) / 512, 512>>>(atoms, embed_atom);

    const int grid = NTOT / MROWS;   // 128
    for (int l = 0; l < LHID; l++)
        layer_kernel<0><<<grid, TPB, SMEM_SZ>>>(l, l & 1, (l & 1) ^ 1,
                                                atoms, dist, gamma_tab);
    layer_kernel<1><<<grid, TPB, SMEM_SZ>>>(6, 0, 1, atoms, dist, gamma_tab);
    layer_kernel<1><<<grid, TPB, SMEM_SZ>>>(7, 1, 0, atoms, dist, gamma_tab);
    layer_kernel<1><<<grid, TPB, SMEM_SZ>>>(8, 0, 1, atoms, dist, gamma_tab);

    tail_kernel<<<256, 256>>>(adducts, W_pred_w, W_pred_b, W_prop_w, W_prop_b, out);
}